// round 10
// baseline (speedup 1.0000x reference)
#include <cuda_runtime.h>
#include <math.h>

#define NN 16384
#define DD 64
#define KK 3
#define G 16
#define CELLS (G * G * G)   // 4096
#define CAP 48              // bucket capacity (P(overflow) ~ 1e-40 for Poisson(4))
#define FULLM 0xFFFFFFFFu

// ---------------- scratch (device globals, no allocation) ----------------
__device__ float g_x[NN * DD];      // features after LN2
__device__ float g_xnorm[NN];       // row L2 norms
__device__ int   g_knn[NN * KK];
__device__ float g_ew[NN * KK];
__device__ float g_dis[NN];         // rsqrt(deg)
__device__ float g_t[NN * DD];      // relu(LN(gcn1 out))

__device__ int    g_cnt[CELLS];
__device__ float4 g_bkt[CELLS * CAP];   // (x, y, z, idx-as-bits)

__device__ __forceinline__ float wsum(float v) {
    #pragma unroll
    for (int o = 16; o > 0; o >>= 1) v += __shfl_xor_sync(FULLM, v, o);
    return v;
}

__device__ __forceinline__ int cell_of(float x, float y, float z) {
    int cx = min(G - 1, max(0, (int)(x * (float)G)));
    int cy = min(G - 1, max(0, (int)(y * (float)G)));
    int cz = min(G - 1, max(0, (int)(z * (float)G)));
    return (cz * G + cy) * G + cx;
}

// ---------------- grid zero ----------------
__global__ void grid_zero() {
    g_cnt[blockIdx.x * 256 + threadIdx.x] = 0;
}

// ---------------- merged: grid_build (blocks 0..63) + LN chain ----------------
__global__ void build_ln(const float* __restrict__ coords,
                         const float* __restrict__ in,
                         const float* __restrict__ g1, const float* __restrict__ b1,
                         const float* __restrict__ g2, const float* __restrict__ b2) {
    if (blockIdx.x < NN / 256) {
        int i = blockIdx.x * 256 + threadIdx.x;
        float x = coords[3 * i], y = coords[3 * i + 1], z = coords[3 * i + 2];
        int c = cell_of(x, y, z);
        int pos = atomicAdd(&g_cnt[c], 1);
        if (pos < CAP) g_bkt[c * CAP + pos] = make_float4(x, y, z, __int_as_float(i));
        return;
    }
    int bb = blockIdx.x - NN / 256;
    int lane = threadIdx.x & 31;
    int ty = threadIdx.x >> 5;
    int i = bb * 8 + ty;
    const float* row = in + (size_t)i * DD;
    float a0 = row[lane], a1 = row[lane + 32];

    float m = wsum(a0 + a1) * (1.0f / 64.0f);
    float d0 = a0 - m, d1 = a1 - m;
    float v = wsum(d0 * d0 + d1 * d1) * (1.0f / 64.0f);
    float inv = rsqrtf(v + 1e-5f);
    float y0 = d0 * inv * g1[lane] + b1[lane];
    float y1 = d1 * inv * g1[lane + 32] + b1[lane + 32];

    y0 *= 2.0f; y1 *= 2.0f;   // x = x + x

    m = wsum(y0 + y1) * (1.0f / 64.0f);
    d0 = y0 - m; d1 = y1 - m;
    v = wsum(d0 * d0 + d1 * d1) * (1.0f / 64.0f);
    inv = rsqrtf(v + 1e-5f);
    float x0 = d0 * inv * g2[lane] + b2[lane];
    float x1 = d1 * inv * g2[lane + 32] + b2[lane + 32];

    g_x[(size_t)i * DD + lane] = x0;
    g_x[(size_t)i * DD + lane + 32] = x1;

    float s = wsum(x0 * x0 + x1 * x1);
    if (lane == 0) g_xnorm[i] = fmaxf(sqrtf(s), 1e-8f);
}

// ---------------- K2: grid KNN, warp per query, LANE PER CELL (round-6 version) ----
__device__ __forceinline__ bool knn_lt(float d, int i, float D, int I) {
    return d < D || (d == D && i < I);
}

__global__ void knn_grid(const float* __restrict__ coords) {
    int q = blockIdx.x * 8 + threadIdx.y;
    int lane = threadIdx.x;

    float qx = coords[3 * q], qy = coords[3 * q + 1], qz = coords[3 * q + 2];
    float qsq = __fadd_rn(__fadd_rn(__fmul_rn(qx, qx), __fmul_rn(qy, qy)),
                          __fmul_rn(qz, qz));
    int cx = min(G - 1, max(0, (int)(qx * (float)G)));
    int cy = min(G - 1, max(0, (int)(qy * (float)G)));
    int cz = min(G - 1, max(0, (int)(qz * (float)G)));
    const float h = 1.0f / (float)G;

    // per-lane disjoint lists
    float d0 = INFINITY, d1 = INFINITY, d2 = INFINITY;
    int i0 = 0x7fffffff, i1 = 0x7fffffff, i2 = 0x7fffffff;

    auto eval_cell_all = [&](int c) {   // this lane evaluates ALL points of cell c
        int cnt = min(g_cnt[c], CAP);
        const float4* bp = &g_bkt[c * CAP];
        for (int t = 0; t < cnt; t++) {
            float4 p = bp[t];
            int j = __float_as_int(p.w);
            if (j == q) continue;
            float psq = __fadd_rn(__fadd_rn(__fmul_rn(p.x, p.x), __fmul_rn(p.y, p.y)),
                                  __fmul_rn(p.z, p.z));
            float dot = __fmaf_rn(qz, p.z, __fmaf_rn(qy, p.y, __fmul_rn(qx, p.x)));
            float d = __fmaf_rn(-2.0f, dot, __fadd_rn(qsq, psq));
            if (knn_lt(d, j, d2, i2)) {
                if (knn_lt(d, j, d1, i1)) {
                    if (knn_lt(d, j, d0, i0)) { d2 = d1; i2 = i1; d1 = d0; i1 = i0; d0 = d; i0 = j; }
                    else                      { d2 = d1; i2 = i1; d1 = d;  i1 = j; }
                } else                        { d2 = d;  i2 = j; }
            }
        }
    };

    // merged copies (recomputed from the live lists at each ring boundary)
    float m0, m1, m2; int n0, n1, n2;
    auto merge_copies = [&]() {
        m0 = d0; m1 = d1; m2 = d2; n0 = i0; n1 = i1; n2 = i2;
        #pragma unroll
        for (int off = 16; off >= 1; off >>= 1) {
            float e0 = __shfl_xor_sync(FULLM, m0, off);
            float e1 = __shfl_xor_sync(FULLM, m1, off);
            float e2 = __shfl_xor_sync(FULLM, m2, off);
            int   j0 = __shfl_xor_sync(FULLM, n0, off);
            int   j1 = __shfl_xor_sync(FULLM, n1, off);
            int   j2 = __shfl_xor_sync(FULLM, n2, off);
            float ee[3] = {e0, e1, e2};
            int   jj[3] = {j0, j1, j2};
            #pragma unroll
            for (int r = 0; r < 3; r++) {
                float d = ee[r]; int i = jj[r];
                if (knn_lt(d, i, m2, n2)) {
                    if (knn_lt(d, i, m1, n1)) {
                        if (knn_lt(d, i, m0, n0)) { m2 = m1; n2 = n1; m1 = m0; n1 = n0; m0 = d; n0 = i; }
                        else                      { m2 = m1; n2 = n1; m1 = d;  n1 = i; }
                    } else                        { m2 = d;  n2 = i; }
                }
            }
        }
    };

    auto stop_ok = [&](int r) -> bool {   // conservative geometric stopping bound
        if (n2 == 0x7fffffff) return false;
        float m = INFINITY;
        if (cx - r > 0)     m = fminf(m, qx - (float)(cx - r) * h);
        if (cx + r < G - 1) m = fminf(m, (float)(cx + r + 1) * h - qx);
        if (cy - r > 0)     m = fminf(m, qy - (float)(cy - r) * h);
        if (cy + r < G - 1) m = fminf(m, (float)(cy + r + 1) * h - qy);
        if (cz - r > 0)     m = fminf(m, qz - (float)(cz - r) * h);
        if (cz + r < G - 1) m = fminf(m, (float)(cz + r + 1) * h - qz);
        return m * m > m2 + 1e-5f;        // rounding skew <= ~3e-6
    };

    // ---- ring 1: 27 cells, one per lane ----
    if (lane < 27) {
        int dz = lane / 9 - 1;
        int dy = (lane % 9) / 3 - 1;
        int dx = lane % 3 - 1;
        int xx = cx + dx, yy = cy + dy, zz = cz + dz;
        if (xx >= 0 && xx < G && yy >= 0 && yy < G && zz >= 0 && zz < G)
            eval_cell_all((zz * G + yy) * G + xx);
    }
    merge_copies();

    bool done;
    {
        bool full = (cx - 1 <= 0 && cx + 1 >= G - 1 && cy - 1 <= 0 && cy + 1 >= G - 1 &&
                     cz - 1 <= 0 && cz + 1 >= G - 1);
        done = full || stop_ok(1);
    }

    // ---- rings r >= 2 (rare): flat shell enumeration, lanes stride cells ----
    for (int r = 2; !done; r++) {
        int side = 2 * r + 1;
        int ncell = side * side * side;
        for (int t = lane; t < ncell; t += 32) {
            int dz = t / (side * side) - r;
            int rem = t % (side * side);
            int dy = rem / side - r;
            int dx = rem % side - r;
            int ma = max(abs(dx), max(abs(dy), abs(dz)));
            if (ma < r) continue;                      // interior already scanned
            int xx = cx + dx, yy = cy + dy, zz = cz + dz;
            if (xx < 0 || xx >= G || yy < 0 || yy >= G || zz < 0 || zz >= G) continue;
            eval_cell_all((zz * G + yy) * G + xx);
        }
        merge_copies();
        bool full = (cx - r <= 0 && cx + r >= G - 1 && cy - r <= 0 && cy + r >= G - 1 &&
                     cz - r <= 0 && cz + r >= G - 1);
        done = full || stop_ok(r);
    }

    if (lane == 0) {
        g_knn[q * 3 + 0] = n0;
        g_knn[q * 3 + 1] = n1;
        g_knn[q * 3 + 2] = n2;
    }
}

// ---------------- K3: edge weights ----------------
__global__ void ew_kernel() {
    int i = blockIdx.x * 8 + threadIdx.y;
    int lane = threadIdx.x;
    float xi0 = g_x[(size_t)i * DD + lane];
    float xi1 = g_x[(size_t)i * DD + lane + 32];
    float ni = g_xnorm[i];

    float deg = 1.0f;
    float ews[KK];
    #pragma unroll
    for (int k = 0; k < KK; k++) {
        int nb = g_knn[i * 3 + k];
        float dot = wsum(xi0 * g_x[(size_t)nb * DD + lane] +
                         xi1 * g_x[(size_t)nb * DD + lane + 32]);
        float z = dot / (g_xnorm[nb] * ni);
        float e = 1.0f / (1.0f + expf(-z));
        ews[k] = e;
        deg += e;
    }
    float dis = rsqrtf(deg);
    if (lane == 0) {
        #pragma unroll
        for (int k = 0; k < KK; k++) g_ew[i * 3 + k] = ews[k];
        g_dis[i] = dis;
    }
}

// ---------------- K4/K5: fused GCN, 4-row-fused matvec ----------------
// Stage 1: each warp aggregates its 4 rows (slots ty, ty+8, ty+16, ty+24) into sZ.
// Stage 2: ONE k-loop; W float2 loaded once per k, FMA'd into 8 accumulators.
// Per-output-element FMA chain remains k-ascending (bit-identical to before).
template <int EPI>
__global__ void gcn_kernel(const float* __restrict__ W, const float* __restrict__ b,
                           const float* __restrict__ lng, const float* __restrict__ lnb,
                           float* __restrict__ out) {
    __shared__ float sW[DD * DD];   // 16 KB
    __shared__ float sZ[32][DD];    // 8 KB
    int lane = threadIdx.x;
    int ty = threadIdx.y;
    int tid = ty * 32 + lane;
    for (int k = tid; k < DD * DD; k += 256) sW[k] = W[k];
    __syncthreads();

    int c0 = 2 * lane;
    const float* xin = (EPI == 1) ? g_x : g_t;
    float2 bb = *(const float2*)&b[c0];

    // ---- stage 1: aggregate 4 rows into sZ ----
    #pragma unroll
    for (int rb = 0; rb < 4; rb++) {
        int s = rb * 8 + ty;
        int i = blockIdx.x * 32 + s;
        float dii = g_dis[i];
        float cs = dii * dii;
        float2 xi = *(const float2*)&xin[(size_t)i * DD + c0];
        float z0 = cs * xi.x, z1 = cs * xi.y;
        #pragma unroll
        for (int k = 0; k < KK; k++) {
            int nb = g_knn[i * 3 + k];
            float c = g_dis[nb] * g_ew[i * 3 + k] * dii;
            float2 xn = *(const float2*)&xin[(size_t)nb * DD + c0];
            z0 = fmaf(c, xn.x, z0);
            z1 = fmaf(c, xn.y, z1);
        }
        sZ[s][c0] = z0;
        sZ[s][c0 + 1] = z1;
    }
    __syncwarp();   // rows of this warp are written only by this warp

    // ---- stage 2: fused 4-row matvec ----
    float a0x = 0.f, a0y = 0.f, a1x = 0.f, a1y = 0.f;
    float a2x = 0.f, a2y = 0.f, a3x = 0.f, a3y = 0.f;
    #pragma unroll
    for (int k = 0; k < DD; k++) {
        float2 w = *(const float2*)&sW[k * DD + c0];
        float zk0 = sZ[ty][k];
        float zk1 = sZ[ty + 8][k];
        float zk2 = sZ[ty + 16][k];
        float zk3 = sZ[ty + 24][k];
        a0x = fmaf(zk0, w.x, a0x); a0y = fmaf(zk0, w.y, a0y);
        a1x = fmaf(zk1, w.x, a1x); a1y = fmaf(zk1, w.y, a1y);
        a2x = fmaf(zk2, w.x, a2x); a2y = fmaf(zk2, w.y, a2y);
        a3x = fmaf(zk3, w.x, a3x); a3y = fmaf(zk3, w.y, a3y);
    }

    // ---- epilogue per row ----
    float accx[4] = {a0x, a1x, a2x, a3x};
    float accy[4] = {a0y, a1y, a2y, a3y};
    #pragma unroll
    for (int r = 0; r < 4; r++) {
        int i = blockIdx.x * 32 + r * 8 + ty;
        float acc0 = accx[r] + bb.x;
        float acc1 = accy[r] + bb.y;
        if (EPI == 1) {
            float m = wsum(acc0 + acc1) * (1.0f / 64.0f);
            float e0 = acc0 - m, e1 = acc1 - m;
            float v = wsum(e0 * e0 + e1 * e1) * (1.0f / 64.0f);
            float inv = rsqrtf(v + 1e-5f);
            float2 o;
            o.x = fmaxf(e0 * inv * lng[c0] + lnb[c0], 0.0f);
            o.y = fmaxf(e1 * inv * lng[c0 + 1] + lnb[c0 + 1], 0.0f);
            *(float2*)&g_t[(size_t)i * DD + c0] = o;
        } else {
            float2 xv = *(const float2*)&g_x[(size_t)i * DD + c0];
            float2 o;
            o.x = fmaf(2.0f, xv.x, acc0);
            o.y = fmaf(2.0f, xv.y, acc1);
            *(float2*)&out[(size_t)i * DD + c0] = o;
        }
    }
}

// ---------------- launch ----------------
extern "C" void kernel_launch(void* const* d_in, const int* in_sizes, int n_in,
                              void* d_out, int out_size) {
    const float* feat   = (const float*)d_in[0];
    const float* coords = (const float*)d_in[4];
    const float* n1g = (const float*)d_in[5];
    const float* n1b = (const float*)d_in[6];
    const float* n2g = (const float*)d_in[7];
    const float* n2b = (const float*)d_in[8];
    const float* gng = (const float*)d_in[9];
    const float* gnb = (const float*)d_in[10];
    const float* W1  = (const float*)d_in[11];
    const float* b1  = (const float*)d_in[12];
    const float* W2  = (const float*)d_in[13];
    const float* b2  = (const float*)d_in[14];
    float* out = (float*)d_out;

    dim3 th(32, 8);
    grid_zero<<<CELLS / 256, 256>>>();
    build_ln<<<NN / 256 + NN / 8, 256>>>(coords, feat, n1g, n1b, n2g, n2b);
    knn_grid<<<NN / 8, th>>>(coords);
    ew_kernel<<<NN / 8, th>>>();
    gcn_kernel<1><<<NN / 32, th>>>(W1, b1, gng, gnb, nullptr);
    gcn_kernel<2><<<NN / 32, th>>>(W2, b2, nullptr, nullptr, out);
}

// round 12
// speedup vs baseline: 1.3063x; 1.3063x over previous
#include <cuda_runtime.h>
#include <math.h>

#define NN 16384
#define DD 64
#define KK 3
#define G 16
#define CELLS (G * G * G)   // 4096
#define CAP 48              // bucket capacity (P(overflow) ~ 1e-40 for Poisson(4))
#define FULLM 0xFFFFFFFFu

// ---------------- scratch (device globals, no allocation) ----------------
__device__ float g_x[NN * DD];      // features after LN2
__device__ float g_xnorm[NN];       // row L2 norms
__device__ int   g_knn[NN * KK];
__device__ float g_ew[NN * KK];
__device__ float g_dis[NN];         // rsqrt(deg)
__device__ float g_t[NN * DD];      // relu(LN(gcn1 out))

__device__ int    g_cnt[CELLS];
__device__ float4 g_bkt[CELLS * CAP];   // (x, y, z, idx-as-bits)

__device__ __forceinline__ float wsum(float v) {
    #pragma unroll
    for (int o = 16; o > 0; o >>= 1) v += __shfl_xor_sync(FULLM, v, o);
    return v;
}

__device__ __forceinline__ int cell_of(float x, float y, float z) {
    int cx = min(G - 1, max(0, (int)(x * (float)G)));
    int cy = min(G - 1, max(0, (int)(y * (float)G)));
    int cz = min(G - 1, max(0, (int)(z * (float)G)));
    return (cz * G + cy) * G + cx;
}

// ---------------- grid zero ----------------
__global__ void grid_zero() {
    g_cnt[blockIdx.x * 256 + threadIdx.x] = 0;
}

// ---------------- merged: grid_build (blocks 0..63) + LN chain ----------------
__global__ void build_ln(const float* __restrict__ coords,
                         const float* __restrict__ in,
                         const float* __restrict__ g1, const float* __restrict__ b1,
                         const float* __restrict__ g2, const float* __restrict__ b2) {
    if (blockIdx.x < NN / 256) {
        int i = blockIdx.x * 256 + threadIdx.x;
        float x = coords[3 * i], y = coords[3 * i + 1], z = coords[3 * i + 2];
        int c = cell_of(x, y, z);
        int pos = atomicAdd(&g_cnt[c], 1);
        if (pos < CAP) g_bkt[c * CAP + pos] = make_float4(x, y, z, __int_as_float(i));
        return;
    }
    int bb = blockIdx.x - NN / 256;
    int lane = threadIdx.x & 31;
    int ty = threadIdx.x >> 5;
    int i = bb * 8 + ty;
    const float* row = in + (size_t)i * DD;
    float a0 = row[lane], a1 = row[lane + 32];

    float m = wsum(a0 + a1) * (1.0f / 64.0f);
    float d0 = a0 - m, d1 = a1 - m;
    float v = wsum(d0 * d0 + d1 * d1) * (1.0f / 64.0f);
    float inv = rsqrtf(v + 1e-5f);
    float y0 = d0 * inv * g1[lane] + b1[lane];
    float y1 = d1 * inv * g1[lane + 32] + b1[lane + 32];

    y0 *= 2.0f; y1 *= 2.0f;   // x = x + x

    m = wsum(y0 + y1) * (1.0f / 64.0f);
    d0 = y0 - m; d1 = y1 - m;
    v = wsum(d0 * d0 + d1 * d1) * (1.0f / 64.0f);
    inv = rsqrtf(v + 1e-5f);
    float x0 = d0 * inv * g2[lane] + b2[lane];
    float x1 = d1 * inv * g2[lane + 32] + b2[lane + 32];

    g_x[(size_t)i * DD + lane] = x0;
    g_x[(size_t)i * DD + lane + 32] = x1;

    float s = wsum(x0 * x0 + x1 * x1);
    if (lane == 0) g_xnorm[i] = fmaxf(sqrtf(s), 1e-8f);
}

// ---------------- K2: grid KNN (round-6 lane-per-cell) + fused edge weights ----
__device__ __forceinline__ bool knn_lt(float d, int i, float D, int I) {
    return d < D || (d == D && i < I);
}

__global__ void knn_ew(const float* __restrict__ coords) {
    int q = blockIdx.x * 8 + threadIdx.y;
    int lane = threadIdx.x;

    float qx = coords[3 * q], qy = coords[3 * q + 1], qz = coords[3 * q + 2];
    float qsq = __fadd_rn(__fadd_rn(__fmul_rn(qx, qx), __fmul_rn(qy, qy)),
                          __fmul_rn(qz, qz));
    int cx = min(G - 1, max(0, (int)(qx * (float)G)));
    int cy = min(G - 1, max(0, (int)(qy * (float)G)));
    int cz = min(G - 1, max(0, (int)(qz * (float)G)));
    const float h = 1.0f / (float)G;

    // per-lane disjoint lists
    float d0 = INFINITY, d1 = INFINITY, d2 = INFINITY;
    int i0 = 0x7fffffff, i1 = 0x7fffffff, i2 = 0x7fffffff;

    auto eval_cell_all = [&](int c) {   // this lane evaluates ALL points of cell c
        int cnt = min(g_cnt[c], CAP);
        const float4* bp = &g_bkt[c * CAP];
        for (int t = 0; t < cnt; t++) {
            float4 p = bp[t];
            int j = __float_as_int(p.w);
            if (j == q) continue;
            float psq = __fadd_rn(__fadd_rn(__fmul_rn(p.x, p.x), __fmul_rn(p.y, p.y)),
                                  __fmul_rn(p.z, p.z));
            float dot = __fmaf_rn(qz, p.z, __fmaf_rn(qy, p.y, __fmul_rn(qx, p.x)));
            float d = __fmaf_rn(-2.0f, dot, __fadd_rn(qsq, psq));
            if (knn_lt(d, j, d2, i2)) {
                if (knn_lt(d, j, d1, i1)) {
                    if (knn_lt(d, j, d0, i0)) { d2 = d1; i2 = i1; d1 = d0; i1 = i0; d0 = d; i0 = j; }
                    else                      { d2 = d1; i2 = i1; d1 = d;  i1 = j; }
                } else                        { d2 = d;  i2 = j; }
            }
        }
    };

    // merged copies (recomputed from the live lists at each ring boundary)
    float m0, m1, m2; int n0, n1, n2;
    auto merge_copies = [&]() {
        m0 = d0; m1 = d1; m2 = d2; n0 = i0; n1 = i1; n2 = i2;
        #pragma unroll
        for (int off = 16; off >= 1; off >>= 1) {
            float e0 = __shfl_xor_sync(FULLM, m0, off);
            float e1 = __shfl_xor_sync(FULLM, m1, off);
            float e2 = __shfl_xor_sync(FULLM, m2, off);
            int   j0 = __shfl_xor_sync(FULLM, n0, off);
            int   j1 = __shfl_xor_sync(FULLM, n1, off);
            int   j2 = __shfl_xor_sync(FULLM, n2, off);
            float ee[3] = {e0, e1, e2};
            int   jj[3] = {j0, j1, j2};
            #pragma unroll
            for (int r = 0; r < 3; r++) {
                float d = ee[r]; int i = jj[r];
                if (knn_lt(d, i, m2, n2)) {
                    if (knn_lt(d, i, m1, n1)) {
                        if (knn_lt(d, i, m0, n0)) { m2 = m1; n2 = n1; m1 = m0; n1 = n0; m0 = d; n0 = i; }
                        else                      { m2 = m1; n2 = n1; m1 = d;  n1 = i; }
                    } else                        { m2 = d;  n2 = i; }
                }
            }
        }
    };

    auto stop_ok = [&](int r) -> bool {   // conservative geometric stopping bound
        if (n2 == 0x7fffffff) return false;
        float m = INFINITY;
        if (cx - r > 0)     m = fminf(m, qx - (float)(cx - r) * h);
        if (cx + r < G - 1) m = fminf(m, (float)(cx + r + 1) * h - qx);
        if (cy - r > 0)     m = fminf(m, qy - (float)(cy - r) * h);
        if (cy + r < G - 1) m = fminf(m, (float)(cy + r + 1) * h - qy);
        if (cz - r > 0)     m = fminf(m, qz - (float)(cz - r) * h);
        if (cz + r < G - 1) m = fminf(m, (float)(cz + r + 1) * h - qz);
        return m * m > m2 + 1e-5f;        // rounding skew <= ~3e-6
    };

    // ---- ring 1: 27 cells, one per lane ----
    if (lane < 27) {
        int dz = lane / 9 - 1;
        int dy = (lane % 9) / 3 - 1;
        int dx = lane % 3 - 1;
        int xx = cx + dx, yy = cy + dy, zz = cz + dz;
        if (xx >= 0 && xx < G && yy >= 0 && yy < G && zz >= 0 && zz < G)
            eval_cell_all((zz * G + yy) * G + xx);
    }
    merge_copies();

    bool done;
    {
        bool full = (cx - 1 <= 0 && cx + 1 >= G - 1 && cy - 1 <= 0 && cy + 1 >= G - 1 &&
                     cz - 1 <= 0 && cz + 1 >= G - 1);
        done = full || stop_ok(1);
    }

    // ---- rings r >= 2 (rare): flat shell enumeration, lanes stride cells ----
    for (int r = 2; !done; r++) {
        int side = 2 * r + 1;
        int ncell = side * side * side;
        for (int t = lane; t < ncell; t += 32) {
            int dz = t / (side * side) - r;
            int rem = t % (side * side);
            int dy = rem / side - r;
            int dx = rem % side - r;
            int ma = max(abs(dx), max(abs(dy), abs(dz)));
            if (ma < r) continue;                      // interior already scanned
            int xx = cx + dx, yy = cy + dy, zz = cz + dz;
            if (xx < 0 || xx >= G || yy < 0 || yy >= G || zz < 0 || zz >= G) continue;
            eval_cell_all((zz * G + yy) * G + xx);
        }
        merge_copies();
        bool full = (cx - r <= 0 && cx + r >= G - 1 && cy - r <= 0 && cy + r >= G - 1 &&
                     cz - r <= 0 && cz + r >= G - 1);
        done = full || stop_ok(r);
    }

    // ---- fused edge weights: neighbors (n0,n1,n2) live in ALL lanes ----
    float xi0 = g_x[(size_t)q * DD + lane];
    float xi1 = g_x[(size_t)q * DD + lane + 32];
    float ni = g_xnorm[q];
    int nbs[KK] = {n0, n1, n2};
    float deg = 1.0f;
    float ews[KK];
    #pragma unroll
    for (int k = 0; k < KK; k++) {
        int nb = nbs[k];
        float dot = wsum(xi0 * g_x[(size_t)nb * DD + lane] +
                         xi1 * g_x[(size_t)nb * DD + lane + 32]);
        float z = dot / (g_xnorm[nb] * ni);
        float e = 1.0f / (1.0f + expf(-z));
        ews[k] = e;
        deg += e;
    }
    float dis = rsqrtf(deg);
    if (lane == 0) {
        #pragma unroll
        for (int k = 0; k < KK; k++) {
            g_knn[q * 3 + k] = nbs[k];
            g_ew[q * 3 + k] = ews[k];
        }
        g_dis[q] = dis;
    }
}

// ---------------- K4/K5: fused GCN (round-6 version: 32 rows/block, col-pair) ------
template <int EPI>
__global__ void gcn_kernel(const float* __restrict__ W, const float* __restrict__ b,
                           const float* __restrict__ lng, const float* __restrict__ lnb,
                           float* __restrict__ out) {
    __shared__ float sW[DD * DD];
    __shared__ float sZ[8][DD];
    int tid = threadIdx.y * 32 + threadIdx.x;
    for (int k = tid; k < DD * DD; k += 256) sW[k] = W[k];
    __syncthreads();

    int lane = threadIdx.x;
    int ty = threadIdx.y;
    int c0 = 2 * lane;
    const float* xin = (EPI == 1) ? g_x : g_t;
    float2 bb = *(const float2*)&b[c0];

    #pragma unroll
    for (int rb = 0; rb < 4; rb++) {
        int i = blockIdx.x * 32 + rb * 8 + ty;

        float dii = g_dis[i];
        float cs = dii * dii;
        float2 xi = *(const float2*)&xin[(size_t)i * DD + c0];
        float z0 = cs * xi.x, z1 = cs * xi.y;
        #pragma unroll
        for (int k = 0; k < KK; k++) {
            int nb = g_knn[i * 3 + k];
            float c = g_dis[nb] * g_ew[i * 3 + k] * dii;
            float2 xn = *(const float2*)&xin[(size_t)nb * DD + c0];
            z0 = fmaf(c, xn.x, z0);
            z1 = fmaf(c, xn.y, z1);
        }
        sZ[ty][c0] = z0;
        sZ[ty][c0 + 1] = z1;
        __syncwarp();

        float acc0 = 0.0f, acc1 = 0.0f;
        #pragma unroll
        for (int k = 0; k < DD; k++) {
            float zk = sZ[ty][k];
            float2 w = *(const float2*)&sW[k * DD + c0];
            acc0 = fmaf(zk, w.x, acc0);
            acc1 = fmaf(zk, w.y, acc1);
        }
        acc0 += bb.x;
        acc1 += bb.y;

        if (EPI == 1) {
            float m = wsum(acc0 + acc1) * (1.0f / 64.0f);
            float e0 = acc0 - m, e1 = acc1 - m;
            float v = wsum(e0 * e0 + e1 * e1) * (1.0f / 64.0f);
            float inv = rsqrtf(v + 1e-5f);
            float2 o;
            o.x = fmaxf(e0 * inv * lng[c0] + lnb[c0], 0.0f);
            o.y = fmaxf(e1 * inv * lng[c0 + 1] + lnb[c0 + 1], 0.0f);
            *(float2*)&g_t[(size_t)i * DD + c0] = o;
        } else {
            float2 xv = *(const float2*)&g_x[(size_t)i * DD + c0];
            float2 o;
            o.x = fmaf(2.0f, xv.x, acc0);
            o.y = fmaf(2.0f, xv.y, acc1);
            *(float2*)&out[(size_t)i * DD + c0] = o;
        }
        __syncwarp();   // sZ reuse in next rb
    }
}

// ---------------- launch ----------------
extern "C" void kernel_launch(void* const* d_in, const int* in_sizes, int n_in,
                              void* d_out, int out_size) {
    const float* feat   = (const float*)d_in[0];
    const float* coords = (const float*)d_in[4];
    const float* n1g = (const float*)d_in[5];
    const float* n1b = (const float*)d_in[6];
    const float* n2g = (const float*)d_in[7];
    const float* n2b = (const float*)d_in[8];
    const float* gng = (const float*)d_in[9];
    const float* gnb = (const float*)d_in[10];
    const float* W1  = (const float*)d_in[11];
    const float* b1  = (const float*)d_in[12];
    const float* W2  = (const float*)d_in[13];
    const float* b2  = (const float*)d_in[14];
    float* out = (float*)d_out;

    dim3 th(32, 8);
    grid_zero<<<CELLS / 256, 256>>>();
    build_ln<<<NN / 256 + NN / 8, 256>>>(coords, feat, n1g, n1b, n2g, n2b);
    knn_ew<<<NN / 8, th>>>(coords);
    gcn_kernel<1><<<NN / 32, th>>>(W1, b1, gng, gnb, nullptr);
    gcn_kernel<2><<<NN / 32, th>>>(W2, b2, nullptr, nullptr, out);
}

// round 13
// speedup vs baseline: 1.3399x; 1.0257x over previous
#include <cuda_runtime.h>
#include <math.h>

#define NN 16384
#define DD 64
#define KK 3
#define G 16
#define CELLS (G * G * G)   // 4096
#define CAP 48              // bucket capacity (P(overflow) ~ 1e-40 for Poisson(4))
#define FULLM 0xFFFFFFFFu
#define GROWS 16            // rows per GCN block (grid = NN/GROWS = 1024)

// ---------------- scratch (device globals, no allocation) ----------------
__device__ float g_x[NN * DD];      // features after LN2
__device__ float g_xnorm[NN];       // row L2 norms
__device__ int   g_knn[NN * KK];
__device__ float g_ew[NN * KK];
__device__ float g_dis[NN];         // rsqrt(deg)
__device__ float g_t[NN * DD];      // relu(LN(gcn1 out))

__device__ int    g_cnt[CELLS];
__device__ float4 g_bkt[CELLS * CAP];   // (x, y, z, idx-as-bits)

__device__ __forceinline__ float wsum(float v) {
    #pragma unroll
    for (int o = 16; o > 0; o >>= 1) v += __shfl_xor_sync(FULLM, v, o);
    return v;
}

__device__ __forceinline__ int cell_of(float x, float y, float z) {
    int cx = min(G - 1, max(0, (int)(x * (float)G)));
    int cy = min(G - 1, max(0, (int)(y * (float)G)));
    int cz = min(G - 1, max(0, (int)(z * (float)G)));
    return (cz * G + cy) * G + cx;
}

// ---------------- grid zero ----------------
__global__ void grid_zero() {
    g_cnt[blockIdx.x * 256 + threadIdx.x] = 0;
}

// ---------------- merged: grid_build (blocks 0..63) + LN chain ----------------
__global__ void build_ln(const float* __restrict__ coords,
                         const float* __restrict__ in,
                         const float* __restrict__ g1, const float* __restrict__ b1,
                         const float* __restrict__ g2, const float* __restrict__ b2) {
    if (blockIdx.x < NN / 256) {
        int i = blockIdx.x * 256 + threadIdx.x;
        float x = coords[3 * i], y = coords[3 * i + 1], z = coords[3 * i + 2];
        int c = cell_of(x, y, z);
        int pos = atomicAdd(&g_cnt[c], 1);
        if (pos < CAP) g_bkt[c * CAP + pos] = make_float4(x, y, z, __int_as_float(i));
        return;
    }
    int bb = blockIdx.x - NN / 256;
    int lane = threadIdx.x & 31;
    int ty = threadIdx.x >> 5;
    int i = bb * 8 + ty;
    const float* row = in + (size_t)i * DD;
    float a0 = row[lane], a1 = row[lane + 32];

    float m = wsum(a0 + a1) * (1.0f / 64.0f);
    float d0 = a0 - m, d1 = a1 - m;
    float v = wsum(d0 * d0 + d1 * d1) * (1.0f / 64.0f);
    float inv = rsqrtf(v + 1e-5f);
    float y0 = d0 * inv * g1[lane] + b1[lane];
    float y1 = d1 * inv * g1[lane + 32] + b1[lane + 32];

    y0 *= 2.0f; y1 *= 2.0f;   // x = x + x

    m = wsum(y0 + y1) * (1.0f / 64.0f);
    d0 = y0 - m; d1 = y1 - m;
    v = wsum(d0 * d0 + d1 * d1) * (1.0f / 64.0f);
    inv = rsqrtf(v + 1e-5f);
    float x0 = d0 * inv * g2[lane] + b2[lane];
    float x1 = d1 * inv * g2[lane + 32] + b2[lane + 32];

    g_x[(size_t)i * DD + lane] = x0;
    g_x[(size_t)i * DD + lane + 32] = x1;

    float s = wsum(x0 * x0 + x1 * x1);
    if (lane == 0) g_xnorm[i] = fmaxf(sqrtf(s), 1e-8f);
}

// ---------------- K2: grid KNN (lane-per-cell) + fused edge weights ----
__device__ __forceinline__ bool knn_lt(float d, int i, float D, int I) {
    return d < D || (d == D && i < I);
}

__global__ void knn_ew(const float* __restrict__ coords) {
    int q = blockIdx.x * 8 + threadIdx.y;
    int lane = threadIdx.x;

    float qx = coords[3 * q], qy = coords[3 * q + 1], qz = coords[3 * q + 2];
    float qsq = __fadd_rn(__fadd_rn(__fmul_rn(qx, qx), __fmul_rn(qy, qy)),
                          __fmul_rn(qz, qz));
    int cx = min(G - 1, max(0, (int)(qx * (float)G)));
    int cy = min(G - 1, max(0, (int)(qy * (float)G)));
    int cz = min(G - 1, max(0, (int)(qz * (float)G)));
    const float h = 1.0f / (float)G;

    // per-lane disjoint lists
    float d0 = INFINITY, d1 = INFINITY, d2 = INFINITY;
    int i0 = 0x7fffffff, i1 = 0x7fffffff, i2 = 0x7fffffff;

    auto eval_cell_all = [&](int c) {   // this lane evaluates ALL points of cell c
        int cnt = min(g_cnt[c], CAP);
        const float4* bp = &g_bkt[c * CAP];
        for (int t = 0; t < cnt; t++) {
            float4 p = bp[t];
            int j = __float_as_int(p.w);
            if (j == q) continue;
            float psq = __fadd_rn(__fadd_rn(__fmul_rn(p.x, p.x), __fmul_rn(p.y, p.y)),
                                  __fmul_rn(p.z, p.z));
            float dot = __fmaf_rn(qz, p.z, __fmaf_rn(qy, p.y, __fmul_rn(qx, p.x)));
            float d = __fmaf_rn(-2.0f, dot, __fadd_rn(qsq, psq));
            if (knn_lt(d, j, d2, i2)) {
                if (knn_lt(d, j, d1, i1)) {
                    if (knn_lt(d, j, d0, i0)) { d2 = d1; i2 = i1; d1 = d0; i1 = i0; d0 = d; i0 = j; }
                    else                      { d2 = d1; i2 = i1; d1 = d;  i1 = j; }
                } else                        { d2 = d;  i2 = j; }
            }
        }
    };

    // merged copies (recomputed from the live lists at each ring boundary)
    float m0, m1, m2; int n0, n1, n2;
    auto merge_copies = [&]() {
        m0 = d0; m1 = d1; m2 = d2; n0 = i0; n1 = i1; n2 = i2;
        #pragma unroll
        for (int off = 16; off >= 1; off >>= 1) {
            float e0 = __shfl_xor_sync(FULLM, m0, off);
            float e1 = __shfl_xor_sync(FULLM, m1, off);
            float e2 = __shfl_xor_sync(FULLM, m2, off);
            int   j0 = __shfl_xor_sync(FULLM, n0, off);
            int   j1 = __shfl_xor_sync(FULLM, n1, off);
            int   j2 = __shfl_xor_sync(FULLM, n2, off);
            float ee[3] = {e0, e1, e2};
            int   jj[3] = {j0, j1, j2};
            #pragma unroll
            for (int r = 0; r < 3; r++) {
                float d = ee[r]; int i = jj[r];
                if (knn_lt(d, i, m2, n2)) {
                    if (knn_lt(d, i, m1, n1)) {
                        if (knn_lt(d, i, m0, n0)) { m2 = m1; n2 = n1; m1 = m0; n1 = n0; m0 = d; n0 = i; }
                        else                      { m2 = m1; n2 = n1; m1 = d;  n1 = i; }
                    } else                        { m2 = d;  n2 = i; }
                }
            }
        }
    };

    auto stop_ok = [&](int r) -> bool {   // conservative geometric stopping bound
        if (n2 == 0x7fffffff) return false;
        float m = INFINITY;
        if (cx - r > 0)     m = fminf(m, qx - (float)(cx - r) * h);
        if (cx + r < G - 1) m = fminf(m, (float)(cx + r + 1) * h - qx);
        if (cy - r > 0)     m = fminf(m, qy - (float)(cy - r) * h);
        if (cy + r < G - 1) m = fminf(m, (float)(cy + r + 1) * h - qy);
        if (cz - r > 0)     m = fminf(m, qz - (float)(cz - r) * h);
        if (cz + r < G - 1) m = fminf(m, (float)(cz + r + 1) * h - qz);
        return m * m > m2 + 1e-5f;        // rounding skew <= ~3e-6
    };

    // ---- ring 1: 27 cells, one per lane ----
    if (lane < 27) {
        int dz = lane / 9 - 1;
        int dy = (lane % 9) / 3 - 1;
        int dx = lane % 3 - 1;
        int xx = cx + dx, yy = cy + dy, zz = cz + dz;
        if (xx >= 0 && xx < G && yy >= 0 && yy < G && zz >= 0 && zz < G)
            eval_cell_all((zz * G + yy) * G + xx);
    }
    merge_copies();

    bool done;
    {
        bool full = (cx - 1 <= 0 && cx + 1 >= G - 1 && cy - 1 <= 0 && cy + 1 >= G - 1 &&
                     cz - 1 <= 0 && cz + 1 >= G - 1);
        done = full || stop_ok(1);
    }

    // ---- rings r >= 2 (rare): flat shell enumeration, lanes stride cells ----
    for (int r = 2; !done; r++) {
        int side = 2 * r + 1;
        int ncell = side * side * side;
        for (int t = lane; t < ncell; t += 32) {
            int dz = t / (side * side) - r;
            int rem = t % (side * side);
            int dy = rem / side - r;
            int dx = rem % side - r;
            int ma = max(abs(dx), max(abs(dy), abs(dz)));
            if (ma < r) continue;                      // interior already scanned
            int xx = cx + dx, yy = cy + dy, zz = cz + dz;
            if (xx < 0 || xx >= G || yy < 0 || yy >= G || zz < 0 || zz >= G) continue;
            eval_cell_all((zz * G + yy) * G + xx);
        }
        merge_copies();
        bool full = (cx - r <= 0 && cx + r >= G - 1 && cy - r <= 0 && cy + r >= G - 1 &&
                     cz - r <= 0 && cz + r >= G - 1);
        done = full || stop_ok(r);
    }

    // ---- fused edge weights: neighbors (n0,n1,n2) live in ALL lanes ----
    float xi0 = g_x[(size_t)q * DD + lane];
    float xi1 = g_x[(size_t)q * DD + lane + 32];
    float ni = g_xnorm[q];
    int nbs[KK] = {n0, n1, n2};
    float deg = 1.0f;
    float ews[KK];
    #pragma unroll
    for (int k = 0; k < KK; k++) {
        int nb = nbs[k];
        float dot = wsum(xi0 * g_x[(size_t)nb * DD + lane] +
                         xi1 * g_x[(size_t)nb * DD + lane + 32]);
        float z = dot / (g_xnorm[nb] * ni);
        float e = 1.0f / (1.0f + expf(-z));
        ews[k] = e;
        deg += e;
    }
    float dis = rsqrtf(deg);
    if (lane == 0) {
        #pragma unroll
        for (int k = 0; k < KK; k++) {
            g_knn[q * 3 + k] = nbs[k];
            g_ew[q * 3 + k] = ews[k];
        }
        g_dis[q] = dis;
    }
}

// ---------------- K4/K5: fused GCN (16 rows/block, grid=1024, col-pair) ------
template <int EPI>
__global__ void gcn_kernel(const float* __restrict__ W, const float* __restrict__ b,
                           const float* __restrict__ lng, const float* __restrict__ lnb,
                           float* __restrict__ out) {
    __shared__ float sW[DD * DD];
    __shared__ float sZ[8][DD];
    int tid = threadIdx.y * 32 + threadIdx.x;
    for (int k = tid; k < DD * DD; k += 256) sW[k] = W[k];
    __syncthreads();

    int lane = threadIdx.x;
    int ty = threadIdx.y;
    int c0 = 2 * lane;
    const float* xin = (EPI == 1) ? g_x : g_t;
    float2 bb = *(const float2*)&b[c0];

    #pragma unroll
    for (int rb = 0; rb < GROWS / 8; rb++) {
        int i = blockIdx.x * GROWS + rb * 8 + ty;

        float dii = g_dis[i];
        float cs = dii * dii;
        float2 xi = *(const float2*)&xin[(size_t)i * DD + c0];
        float z0 = cs * xi.x, z1 = cs * xi.y;
        #pragma unroll
        for (int k = 0; k < KK; k++) {
            int nb = g_knn[i * 3 + k];
            float c = g_dis[nb] * g_ew[i * 3 + k] * dii;
            float2 xn = *(const float2*)&xin[(size_t)nb * DD + c0];
            z0 = fmaf(c, xn.x, z0);
            z1 = fmaf(c, xn.y, z1);
        }
        sZ[ty][c0] = z0;
        sZ[ty][c0 + 1] = z1;
        __syncwarp();

        float acc0 = 0.0f, acc1 = 0.0f;
        #pragma unroll
        for (int k = 0; k < DD; k++) {
            float zk = sZ[ty][k];
            float2 w = *(const float2*)&sW[k * DD + c0];
            acc0 = fmaf(zk, w.x, acc0);
            acc1 = fmaf(zk, w.y, acc1);
        }
        acc0 += bb.x;
        acc1 += bb.y;

        if (EPI == 1) {
            float m = wsum(acc0 + acc1) * (1.0f / 64.0f);
            float e0 = acc0 - m, e1 = acc1 - m;
            float v = wsum(e0 * e0 + e1 * e1) * (1.0f / 64.0f);
            float inv = rsqrtf(v + 1e-5f);
            float2 o;
            o.x = fmaxf(e0 * inv * lng[c0] + lnb[c0], 0.0f);
            o.y = fmaxf(e1 * inv * lng[c0 + 1] + lnb[c0 + 1], 0.0f);
            *(float2*)&g_t[(size_t)i * DD + c0] = o;
        } else {
            float2 xv = *(const float2*)&g_x[(size_t)i * DD + c0];
            float2 o;
            o.x = fmaf(2.0f, xv.x, acc0);
            o.y = fmaf(2.0f, xv.y, acc1);
            *(float2*)&out[(size_t)i * DD + c0] = o;
        }
        __syncwarp();   // sZ reuse in next rb
    }
}

// ---------------- launch ----------------
extern "C" void kernel_launch(void* const* d_in, const int* in_sizes, int n_in,
                              void* d_out, int out_size) {
    const float* feat   = (const float*)d_in[0];
    const float* coords = (const float*)d_in[4];
    const float* n1g = (const float*)d_in[5];
    const float* n1b = (const float*)d_in[6];
    const float* n2g = (const float*)d_in[7];
    const float* n2b = (const float*)d_in[8];
    const float* gng = (const float*)d_in[9];
    const float* gnb = (const float*)d_in[10];
    const float* W1  = (const float*)d_in[11];
    const float* b1  = (const float*)d_in[12];
    const float* W2  = (const float*)d_in[13];
    const float* b2  = (const float*)d_in[14];
    float* out = (float*)d_out;

    dim3 th(32, 8);
    grid_zero<<<CELLS / 256, 256>>>();
    build_ln<<<NN / 256 + NN / 8, 256>>>(coords, feat, n1g, n1b, n2g, n2b);
    knn_ew<<<NN / 8, th>>>(coords);
    gcn_kernel<1><<<NN / GROWS, th>>>(W1, b1, gng, gnb, nullptr);
    gcn_kernel<2><<<NN / GROWS, th>>>(W2, b2, nullptr, nullptr, out);
}

// round 15
// speedup vs baseline: 1.4909x; 1.1127x over previous
#include <cuda_runtime.h>
#include <math.h>

#define NN 16384
#define DD 64
#define KK 3
#define G 16
#define CELLS (G * G * G)   // 4096
#define CAP 48              // bucket capacity (P(overflow) ~ 1e-40 for Poisson(4))
#define FULLM 0xFFFFFFFFu
#define GROWS 16            // rows per GCN block (grid = NN/GROWS = 1024)

// ---------------- scratch (device globals, no allocation) ----------------
__device__ float g_x[NN * DD];      // features after LN2
__device__ float g_xnorm[NN];       // row L2 norms
__device__ int   g_knn[NN * KK];
__device__ float g_ew[NN * KK];
__device__ float g_dis[NN];         // rsqrt(deg)
__device__ float g_t[NN * DD];      // relu(LN(gcn1 out))

__device__ int    g_cnt[CELLS];
__device__ float4 g_bkt[CELLS * CAP];   // (x, y, z, idx-as-bits)

__device__ __forceinline__ float wsum(float v) {
    #pragma unroll
    for (int o = 16; o > 0; o >>= 1) v += __shfl_xor_sync(FULLM, v, o);
    return v;
}

__device__ __forceinline__ int cell_of(float x, float y, float z) {
    int cx = min(G - 1, max(0, (int)(x * (float)G)));
    int cy = min(G - 1, max(0, (int)(y * (float)G)));
    int cz = min(G - 1, max(0, (int)(z * (float)G)));
    return (cz * G + cy) * G + cx;
}

// ---------------- grid zero ----------------
__global__ void grid_zero() {
    g_cnt[blockIdx.x * 256 + threadIdx.x] = 0;
}

// ---------------- merged: grid_build (blocks 0..63) + LN chain ----------------
__global__ void build_ln(const float* __restrict__ coords,
                         const float* __restrict__ in,
                         const float* __restrict__ g1, const float* __restrict__ b1,
                         const float* __restrict__ g2, const float* __restrict__ b2) {
    if (blockIdx.x < NN / 256) {
        int i = blockIdx.x * 256 + threadIdx.x;
        float x = coords[3 * i], y = coords[3 * i + 1], z = coords[3 * i + 2];
        int c = cell_of(x, y, z);
        int pos = atomicAdd(&g_cnt[c], 1);
        if (pos < CAP) g_bkt[c * CAP + pos] = make_float4(x, y, z, __int_as_float(i));
        return;
    }
    int bb = blockIdx.x - NN / 256;
    int lane = threadIdx.x & 31;
    int ty = threadIdx.x >> 5;
    int i = bb * 8 + ty;
    const float* row = in + (size_t)i * DD;
    float a0 = row[lane], a1 = row[lane + 32];

    float m = wsum(a0 + a1) * (1.0f / 64.0f);
    float d0 = a0 - m, d1 = a1 - m;
    float v = wsum(d0 * d0 + d1 * d1) * (1.0f / 64.0f);
    float inv = rsqrtf(v + 1e-5f);
    float y0 = d0 * inv * g1[lane] + b1[lane];
    float y1 = d1 * inv * g1[lane + 32] + b1[lane + 32];

    y0 *= 2.0f; y1 *= 2.0f;   // x = x + x

    m = wsum(y0 + y1) * (1.0f / 64.0f);
    d0 = y0 - m; d1 = y1 - m;
    v = wsum(d0 * d0 + d1 * d1) * (1.0f / 64.0f);
    inv = rsqrtf(v + 1e-5f);
    float x0 = d0 * inv * g2[lane] + b2[lane];
    float x1 = d1 * inv * g2[lane + 32] + b2[lane + 32];

    g_x[(size_t)i * DD + lane] = x0;
    g_x[(size_t)i * DD + lane + 32] = x1;

    float s = wsum(x0 * x0 + x1 * x1);
    if (lane == 0) g_xnorm[i] = fmaxf(sqrtf(s), 1e-8f);
}

// ---------------- K2: grid KNN (lane-per-cell) + fused edge weights ----
__device__ __forceinline__ bool knn_lt(float d, int i, float D, int I) {
    return d < D || (d == D && i < I);
}

__global__ void knn_ew(const float* __restrict__ coords) {
    int q = blockIdx.x * 8 + threadIdx.y;
    int lane = threadIdx.x;

    float qx = coords[3 * q], qy = coords[3 * q + 1], qz = coords[3 * q + 2];
    float qsq = __fadd_rn(__fadd_rn(__fmul_rn(qx, qx), __fmul_rn(qy, qy)),
                          __fmul_rn(qz, qz));
    int cx = min(G - 1, max(0, (int)(qx * (float)G)));
    int cy = min(G - 1, max(0, (int)(qy * (float)G)));
    int cz = min(G - 1, max(0, (int)(qz * (float)G)));
    const float h = 1.0f / (float)G;

    // per-lane disjoint lists
    float d0 = INFINITY, d1 = INFINITY, d2 = INFINITY;
    int i0 = 0x7fffffff, i1 = 0x7fffffff, i2 = 0x7fffffff;

    auto eval_cell_all = [&](int c) {   // this lane evaluates ALL points of cell c
        int cnt = min(g_cnt[c], CAP);
        const float4* bp = &g_bkt[c * CAP];
        for (int t = 0; t < cnt; t++) {
            float4 p = bp[t];
            int j = __float_as_int(p.w);
            if (j == q) continue;
            float psq = __fadd_rn(__fadd_rn(__fmul_rn(p.x, p.x), __fmul_rn(p.y, p.y)),
                                  __fmul_rn(p.z, p.z));
            float dot = __fmaf_rn(qz, p.z, __fmaf_rn(qy, p.y, __fmul_rn(qx, p.x)));
            float d = __fmaf_rn(-2.0f, dot, __fadd_rn(qsq, psq));
            if (knn_lt(d, j, d2, i2)) {
                if (knn_lt(d, j, d1, i1)) {
                    if (knn_lt(d, j, d0, i0)) { d2 = d1; i2 = i1; d1 = d0; i1 = i0; d0 = d; i0 = j; }
                    else                      { d2 = d1; i2 = i1; d1 = d;  i1 = j; }
                } else                        { d2 = d;  i2 = j; }
            }
        }
    };

    // merged copies (recomputed from the live lists at each ring boundary)
    float m0, m1, m2; int n0, n1, n2;
    auto merge_copies = [&]() {
        m0 = d0; m1 = d1; m2 = d2; n0 = i0; n1 = i1; n2 = i2;
        #pragma unroll
        for (int off = 16; off >= 1; off >>= 1) {
            float e0 = __shfl_xor_sync(FULLM, m0, off);
            float e1 = __shfl_xor_sync(FULLM, m1, off);
            float e2 = __shfl_xor_sync(FULLM, m2, off);
            int   j0 = __shfl_xor_sync(FULLM, n0, off);
            int   j1 = __shfl_xor_sync(FULLM, n1, off);
            int   j2 = __shfl_xor_sync(FULLM, n2, off);
            float ee[3] = {e0, e1, e2};
            int   jj[3] = {j0, j1, j2};
            #pragma unroll
            for (int r = 0; r < 3; r++) {
                float d = ee[r]; int i = jj[r];
                if (knn_lt(d, i, m2, n2)) {
                    if (knn_lt(d, i, m1, n1)) {
                        if (knn_lt(d, i, m0, n0)) { m2 = m1; n2 = n1; m1 = m0; n1 = n0; m0 = d; n0 = i; }
                        else                      { m2 = m1; n2 = n1; m1 = d;  n1 = i; }
                    } else                        { m2 = d;  n2 = i; }
                }
            }
        }
    };

    auto stop_ok = [&](int r) -> bool {   // conservative geometric stopping bound
        if (n2 == 0x7fffffff) return false;
        float m = INFINITY;
        if (cx - r > 0)     m = fminf(m, qx - (float)(cx - r) * h);
        if (cx + r < G - 1) m = fminf(m, (float)(cx + r + 1) * h - qx);
        if (cy - r > 0)     m = fminf(m, qy - (float)(cy - r) * h);
        if (cy + r < G - 1) m = fminf(m, (float)(cy + r + 1) * h - qy);
        if (cz - r > 0)     m = fminf(m, qz - (float)(cz - r) * h);
        if (cz + r < G - 1) m = fminf(m, (float)(cz + r + 1) * h - qz);
        return m * m > m2 + 1e-5f;        // rounding skew <= ~3e-6
    };

    // ---- ring 1: 27 cells, one per lane ----
    if (lane < 27) {
        int dz = lane / 9 - 1;
        int dy = (lane % 9) / 3 - 1;
        int dx = lane % 3 - 1;
        int xx = cx + dx, yy = cy + dy, zz = cz + dz;
        if (xx >= 0 && xx < G && yy >= 0 && yy < G && zz >= 0 && zz < G)
            eval_cell_all((zz * G + yy) * G + xx);
    }
    merge_copies();

    bool done;
    {
        bool full = (cx - 1 <= 0 && cx + 1 >= G - 1 && cy - 1 <= 0 && cy + 1 >= G - 1 &&
                     cz - 1 <= 0 && cz + 1 >= G - 1);
        done = full || stop_ok(1);
    }

    // ---- rings r >= 2 (rare): flat shell enumeration, lanes stride cells ----
    for (int r = 2; !done; r++) {
        int side = 2 * r + 1;
        int ncell = side * side * side;
        for (int t = lane; t < ncell; t += 32) {
            int dz = t / (side * side) - r;
            int rem = t % (side * side);
            int dy = rem / side - r;
            int dx = rem % side - r;
            int ma = max(abs(dx), max(abs(dy), abs(dz)));
            if (ma < r) continue;                      // interior already scanned
            int xx = cx + dx, yy = cy + dy, zz = cz + dz;
            if (xx < 0 || xx >= G || yy < 0 || yy >= G || zz < 0 || zz >= G) continue;
            eval_cell_all((zz * G + yy) * G + xx);
        }
        merge_copies();
        bool full = (cx - r <= 0 && cx + r >= G - 1 && cy - r <= 0 && cy + r >= G - 1 &&
                     cz - r <= 0 && cz + r >= G - 1);
        done = full || stop_ok(r);
    }

    // ---- fused edge weights: neighbors (n0,n1,n2) live in ALL lanes ----
    float xi0 = g_x[(size_t)q * DD + lane];
    float xi1 = g_x[(size_t)q * DD + lane + 32];
    float ni = g_xnorm[q];
    int nbs[KK] = {n0, n1, n2};
    float deg = 1.0f;
    float ews[KK];
    #pragma unroll
    for (int k = 0; k < KK; k++) {
        int nb = nbs[k];
        float dot = wsum(xi0 * g_x[(size_t)nb * DD + lane] +
                         xi1 * g_x[(size_t)nb * DD + lane + 32]);
        float z = dot / (g_xnorm[nb] * ni);
        float e = 1.0f / (1.0f + expf(-z));
        ews[k] = e;
        deg += e;
    }
    float dis = rsqrtf(deg);
    if (lane == 0) {
        #pragma unroll
        for (int k = 0; k < KK; k++) {
            g_knn[q * 3 + k] = nbs[k];
            g_ew[q * 3 + k] = ews[k];
        }
        g_dis[q] = dis;
    }
}

// ---------------- K4/K5: fused GCN (16 rows/block, 2-row-fused k-loop) ------
// Warp ty owns rows 2ty and 2ty+1. One k-loop: W float2 loaded ONCE per k and
// FMA'd into both rows' accumulators (4 per thread). Per-output-element FMA
// chains stay k-ascending (bit-identical). Epilogue identical, run per row.
template <int EPI>
__global__ void gcn_kernel(const float* __restrict__ W, const float* __restrict__ b,
                           const float* __restrict__ lng, const float* __restrict__ lnb,
                           float* __restrict__ out) {
    __shared__ float sW[DD * DD];      // 16 KB
    __shared__ float sZ[GROWS][DD];    // 4 KB
    int lane = threadIdx.x;
    int ty = threadIdx.y;
    int tid = ty * 32 + lane;
    for (int k = tid; k < DD * DD; k += 256) sW[k] = W[k];
    __syncthreads();

    int c0 = 2 * lane;
    const float* xin = (EPI == 1) ? g_x : g_t;
    float2 bb = *(const float2*)&b[c0];

    // ---- stage 1: aggregate this warp's 2 rows into sZ ----
    #pragma unroll
    for (int rr = 0; rr < 2; rr++) {
        int s = 2 * ty + rr;
        int i = blockIdx.x * GROWS + s;
        float dii = g_dis[i];
        float cs = dii * dii;
        float2 xi = *(const float2*)&xin[(size_t)i * DD + c0];
        float z0 = cs * xi.x, z1 = cs * xi.y;
        #pragma unroll
        for (int k = 0; k < KK; k++) {
            int nb = g_knn[i * 3 + k];
            float c = g_dis[nb] * g_ew[i * 3 + k] * dii;
            float2 xn = *(const float2*)&xin[(size_t)nb * DD + c0];
            z0 = fmaf(c, xn.x, z0);
            z1 = fmaf(c, xn.y, z1);
        }
        sZ[s][c0] = z0;
        sZ[s][c0 + 1] = z1;
    }
    __syncwarp();   // rows of this warp written/read only by this warp

    // ---- stage 2: 2-row fused matvec (W float2 loaded once per k) ----
    float a0x = 0.f, a0y = 0.f, a1x = 0.f, a1y = 0.f;
    #pragma unroll
    for (int k = 0; k < DD; k++) {
        float2 w = *(const float2*)&sW[k * DD + c0];
        float zk0 = sZ[2 * ty][k];
        float zk1 = sZ[2 * ty + 1][k];
        a0x = fmaf(zk0, w.x, a0x); a0y = fmaf(zk0, w.y, a0y);
        a1x = fmaf(zk1, w.x, a1x); a1y = fmaf(zk1, w.y, a1y);
    }

    // ---- epilogue per row (identical math to previous version) ----
    float accx[2] = {a0x, a1x};
    float accy[2] = {a0y, a1y};
    #pragma unroll
    for (int rr = 0; rr < 2; rr++) {
        int i = blockIdx.x * GROWS + 2 * ty + rr;
        float acc0 = accx[rr] + bb.x;
        float acc1 = accy[rr] + bb.y;
        if (EPI == 1) {
            float m = wsum(acc0 + acc1) * (1.0f / 64.0f);
            float e0 = acc0 - m, e1 = acc1 - m;
            float v = wsum(e0 * e0 + e1 * e1) * (1.0f / 64.0f);
            float inv = rsqrtf(v + 1e-5f);
            float2 o;
            o.x = fmaxf(e0 * inv * lng[c0] + lnb[c0], 0.0f);
            o.y = fmaxf(e1 * inv * lng[c0 + 1] + lnb[c0 + 1], 0.0f);
            *(float2*)&g_t[(size_t)i * DD + c0] = o;
        } else {
            float2 xv = *(const float2*)&g_x[(size_t)i * DD + c0];
            float2 o;
            o.x = fmaf(2.0f, xv.x, acc0);
            o.y = fmaf(2.0f, xv.y, acc1);
            *(float2*)&out[(size_t)i * DD + c0] = o;
        }
    }
}

// ---------------- launch ----------------
extern "C" void kernel_launch(void* const* d_in, const int* in_sizes, int n_in,
                              void* d_out, int out_size) {
    const float* feat   = (const float*)d_in[0];
    const float* coords = (const float*)d_in[4];
    const float* n1g = (const float*)d_in[5];
    const float* n1b = (const float*)d_in[6];
    const float* n2g = (const float*)d_in[7];
    const float* n2b = (const float*)d_in[8];
    const float* gng = (const float*)d_in[9];
    const float* gnb = (const float*)d_in[10];
    const float* W1  = (const float*)d_in[11];
    const float* b1  = (const float*)d_in[12];
    const float* W2  = (const float*)d_in[13];
    const float* b2  = (const float*)d_in[14];
    float* out = (float*)d_out;

    dim3 th(32, 8);
    grid_zero<<<CELLS / 256, 256>>>();
    build_ln<<<NN / 256 + NN / 8, 256>>>(coords, feat, n1g, n1b, n2g, n2b);
    knn_ew<<<NN / 8, th>>>(coords);
    gcn_kernel<1><<<NN / GROWS, th>>>(W1, b1, gng, gnb, nullptr);
    gcn_kernel<2><<<NN / GROWS, th>>>(W2, b2, nullptr, nullptr, out);
}